// round 1
// baseline (speedup 1.0000x reference)
#include <cuda_runtime.h>
#include <cuda_bf16.h>
#include <cstdint>

// Problem constants (shapes are fixed by the dataset; runtime values derived
// from in_sizes as a guard).
#define MAX_NU 160000
#define MAX_NM 60000
#define DIM 64
#define COEF (13.0f / 12.0f)   // 1/2 + 1/3 + 1/4 applied to the (identical) per-layer aggregation

// Scratch (no allocations allowed)
__device__ int   g_deg_u[MAX_NU];
__device__ int   g_deg_m[MAX_NM];
__device__ float g_inv_u[MAX_NU];
__device__ float g_inv_m[MAX_NM];

// 16-byte vector reduction into global memory (sm_90+)
__device__ __forceinline__ void red_add_v4(float4* addr, float x, float y, float z, float w) {
    asm volatile("red.global.add.v4.f32 [%0], {%1, %2, %3, %4};"
                 :: "l"(addr), "f"(x), "f"(y), "f"(z), "f"(w) : "memory");
}

// ---------------------------------------------------------------------------
// 1. zero degree counters
__global__ void k_zero_deg(int nu, int nm) {
    int i = blockIdx.x * blockDim.x + threadIdx.x;
    if (i < nu) g_deg_u[i] = 0;
    if (i < nm) g_deg_m[i] = 0;
}

// 2. count degrees
__global__ void k_count_deg(const int* __restrict__ ef, const int* __restrict__ et, int E) {
    int i = blockIdx.x * blockDim.x + threadIdx.x;
    int stride = gridDim.x * blockDim.x;
    for (; i < E; i += stride) {
        atomicAdd(&g_deg_m[ef[i]], 1);
        atomicAdd(&g_deg_u[et[i]], 1);
    }
}

// 3. inverse sqrt degrees
__global__ void k_inv(int nu, int nm) {
    int i = blockIdx.x * blockDim.x + threadIdx.x;
    if (i < nu) {
        int d = g_deg_u[i];
        g_inv_u[i] = (d > 0) ? rsqrtf((float)d) : 0.0f;
    }
    if (i < nm) {
        int d = g_deg_m[i];
        g_inv_m[i] = (d > 0) ? rsqrtf((float)d) : 0.0f;
    }
}

// 4. res_u = x_u ; res_m = x_m  (vectorized copy into d_out regions)
__global__ void k_init_res(const float4* __restrict__ xu, const float4* __restrict__ xm,
                           float4* __restrict__ ru, float4* __restrict__ rm,
                           int nu4, int nm4) {
    int i = blockIdx.x * blockDim.x + threadIdx.x;
    int stride = gridDim.x * blockDim.x;
    for (int j = i; j < nu4; j += stride) ru[j] = xu[j];
    for (int j = i; j < nm4; j += stride) rm[j] = xm[j];
}

// 5. edge scatter: one warp per edge.
//    lanes 0..15  : res_u[t] += n * x_m[f]   (16 lanes x float4 = 64 floats)
//    lanes 16..31 : res_m[f] += n * x_u[t]
__global__ void k_edge_scatter(const int* __restrict__ ef, const int* __restrict__ et,
                               const float4* __restrict__ xu, const float4* __restrict__ xm,
                               float4* __restrict__ ru, float4* __restrict__ rm,
                               int E) {
    int gtid = blockIdx.x * blockDim.x + threadIdx.x;
    int e    = gtid >> 5;
    int lane = gtid & 31;
    if (e >= E) return;

    int f = ef[e];   // movie
    int t = et[e];   // user
    float n = g_inv_m[f] * g_inv_u[t] * COEF;   // broadcast load, warp-uniform

    if (lane < 16) {
        float4 v = xm[f * 16 + lane];
        red_add_v4(&ru[t * 16 + lane], n * v.x, n * v.y, n * v.z, n * v.w);
    } else {
        int l = lane - 16;
        float4 v = xu[t * 16 + l];
        red_add_v4(&rm[f * 16 + l], n * v.x, n * v.y, n * v.z, n * v.w);
    }
}

// 6. scores: one warp per label edge, 2 floats per lane, warp-reduce dot
__global__ void k_scores(const int* __restrict__ lm, const int* __restrict__ lu,
                         const float2* __restrict__ ru, const float2* __restrict__ rm,
                         float* __restrict__ out, int L) {
    int gtid = blockIdx.x * blockDim.x + threadIdx.x;
    int l    = gtid >> 5;
    int lane = gtid & 31;
    if (l >= L) return;

    int m = lm[l];
    int u = lu[l];
    float2 a = ru[u * 32 + lane];
    float2 b = rm[m * 32 + lane];
    float s = a.x * b.x + a.y * b.y;

    #pragma unroll
    for (int off = 16; off > 0; off >>= 1)
        s += __shfl_down_sync(0xFFFFFFFFu, s, off);

    if (lane == 0) out[l] = s;
}

// ---------------------------------------------------------------------------
extern "C" void kernel_launch(void* const* d_in, const int* in_sizes, int n_in,
                              void* d_out, int out_size) {
    const float* emb_user  = (const float*)d_in[0];   // [NU, 64]
    const float* emb_movie = (const float*)d_in[1];   // [NM, 64]
    // d_in[2], d_in[3]: node_id aranges — identity lookup, unused
    const int* edge_from   = (const int*)d_in[4];     // [E] movie idx
    const int* edge_to     = (const int*)d_in[5];     // [E] user idx
    const int* label_movie = (const int*)d_in[6];     // [L]
    const int* label_user  = (const int*)d_in[7];     // [L]

    int NU = in_sizes[0] / DIM;
    int NM = in_sizes[1] / DIM;
    int E  = in_sizes[4];
    int L  = in_sizes[6];

    float* out    = (float*)d_out;
    float* scores = out;                    // [L]
    float* res_u  = out + L;                // [NU*64], 16B-aligned (L*4 % 16 == 0)
    float* res_m  = out + L + NU * DIM;     // [NM*64]

    const float4* xu4 = (const float4*)emb_user;
    const float4* xm4 = (const float4*)emb_movie;
    float4* ru4 = (float4*)res_u;
    float4* rm4 = (float4*)res_m;

    int nmax = (NU > NM) ? NU : NM;

    // 1. zero degrees
    k_zero_deg<<<(nmax + 255) / 256, 256>>>(NU, NM);

    // 2. count degrees (grid-stride)
    k_count_deg<<<4096, 256>>>(edge_from, edge_to, E);

    // 3. inverse sqrt
    k_inv<<<(nmax + 255) / 256, 256>>>(NU, NM);

    // 4. init res = x
    {
        int nu4 = NU * (DIM / 4);
        int nm4 = NM * (DIM / 4);
        k_init_res<<<4096, 256>>>(xu4, xm4, ru4, rm4, nu4, nm4);
    }

    // 5. edge scatter: 1 warp per edge
    {
        long long threads = (long long)E * 32;
        int blocks = (int)((threads + 255) / 256);
        k_edge_scatter<<<blocks, 256>>>(edge_from, edge_to, xu4, xm4, ru4, rm4, E);
    }

    // 6. label-edge dot products
    {
        long long threads = (long long)L * 32;
        int blocks = (int)((threads + 255) / 256);
        k_scores<<<blocks, 256>>>(label_movie, label_user,
                                  (const float2*)res_u, (const float2*)res_m,
                                  scores, L);
    }
}

// round 2
// speedup vs baseline: 1.8037x; 1.8037x over previous
#include <cuda_runtime.h>
#include <cuda_bf16.h>
#include <cstdint>

#define MAX_NU 160000
#define MAX_NM 60000
#define MAX_E  5000000
#define DIM 64
#define COEF (13.0f / 12.0f)   // 1/2 + 1/3 + 1/4 : layers all aggregate layer-0 feats

// ---- scratch (static device globals; no allocation allowed) ----------------
__device__ int   g_deg_u[MAX_NU];
__device__ int   g_deg_m[MAX_NM];
__device__ float g_inv_u[MAX_NU];
__device__ float g_inv_m[MAX_NM];
__device__ int   g_off_u[MAX_NU + 1];
__device__ int   g_off_m[MAX_NM + 1];
__device__ int   g_cur_u[MAX_NU];
__device__ int   g_cur_m[MAX_NM];
__device__ int   g_nbr_u[MAX_E];   // for each user: movie neighbors
__device__ int   g_nbr_m[MAX_E];   // for each movie: user neighbors

// ---------------------------------------------------------------------------
__global__ void k_zero_deg(int nu, int nm) {
    int i = blockIdx.x * blockDim.x + threadIdx.x;
    if (i < nu) g_deg_u[i] = 0;
    if (i < nm) g_deg_m[i] = 0;
}

__global__ void k_count_deg(const int* __restrict__ ef, const int* __restrict__ et, int E) {
    int i = blockIdx.x * blockDim.x + threadIdx.x;
    int stride = gridDim.x * blockDim.x;
    for (; i < E; i += stride) {
        atomicAdd(&g_deg_m[ef[i]], 1);
        atomicAdd(&g_deg_u[et[i]], 1);
    }
}

__global__ void k_inv(int nu, int nm) {
    int i = blockIdx.x * blockDim.x + threadIdx.x;
    if (i < nu) {
        int d = g_deg_u[i];
        g_inv_u[i] = (d > 0) ? rsqrtf((float)d) : 0.0f;
    }
    if (i < nm) {
        int d = g_deg_m[i];
        g_inv_m[i] = (d > 0) ? rsqrtf((float)d) : 0.0f;
    }
}

// Exclusive scan, one block per array (blockIdx 0 -> users, 1 -> movies).
// 1024 threads, 4 elements/thread per tile. Writes off[] and cur[] (=off copy).
#define SCAN_T 1024
__global__ void k_scan(int nu, int nm) {
    __shared__ int sh[SCAN_T];
    const int* deg; int* off; int* cur; int n;
    if (blockIdx.x == 0) { deg = g_deg_u; off = g_off_u; cur = g_cur_u; n = nu; }
    else                 { deg = g_deg_m; off = g_off_m; cur = g_cur_m; n = nm; }

    int t = threadIdx.x;
    int carry = 0;
    for (int base = 0; base < n; base += SCAN_T * 4) {
        int idx = base + t * 4;
        int v0 = (idx + 0 < n) ? deg[idx + 0] : 0;
        int v1 = (idx + 1 < n) ? deg[idx + 1] : 0;
        int v2 = (idx + 2 < n) ? deg[idx + 2] : 0;
        int v3 = (idx + 3 < n) ? deg[idx + 3] : 0;
        int s = v0 + v1 + v2 + v3;
        sh[t] = s;
        __syncthreads();
        #pragma unroll
        for (int o = 1; o < SCAN_T; o <<= 1) {
            int tmp = (t >= o) ? sh[t - o] : 0;
            __syncthreads();
            sh[t] += tmp;
            __syncthreads();
        }
        int ex = carry + sh[t] - s;   // exclusive prefix for this thread's chunk
        if (idx + 0 < n) { off[idx + 0] = ex; cur[idx + 0] = ex; } ex += v0;
        if (idx + 1 < n) { off[idx + 1] = ex; cur[idx + 1] = ex; } ex += v1;
        if (idx + 2 < n) { off[idx + 2] = ex; cur[idx + 2] = ex; } ex += v2;
        if (idx + 3 < n) { off[idx + 3] = ex; cur[idx + 3] = ex; }
        carry += sh[SCAN_T - 1];
        __syncthreads();
    }
    if (t == 0) off[n] = carry;
}

// Fill both CSRs (order within a row is arbitrary; sums commute to tolerance).
__global__ void k_fill(const int* __restrict__ ef, const int* __restrict__ et, int E) {
    int i = blockIdx.x * blockDim.x + threadIdx.x;
    int stride = gridDim.x * blockDim.x;
    for (; i < E; i += stride) {
        int f = ef[i];   // movie
        int t = et[i];   // user
        int pu = atomicAdd(&g_cur_u[t], 1);
        g_nbr_u[pu] = f;
        int pm = atomicAdd(&g_cur_m[f], 1);
        g_nbr_m[pm] = t;
    }
}

// Gather: one warp per destination node. Half-warps process neighbors in
// pairs; each half loads one 64-float source row as 16 x float4.
// out[w] = x_self[w] + COEF * inv_self[w] * sum_f inv_src[f] * x_src[f]
__global__ void __launch_bounds__(256)
k_gather(const int* __restrict__ nbr, const int* __restrict__ roff,
         const float4* __restrict__ xsrc, const float4* __restrict__ xself,
         const float* __restrict__ inv_self, const float* __restrict__ inv_src,
         float4* __restrict__ out, int n)
{
    int gtid = blockIdx.x * blockDim.x + threadIdx.x;
    int w = gtid >> 5;
    if (w >= n) return;
    int lane = threadIdx.x & 31;
    int half = lane >> 4;
    int l    = lane & 15;

    int s = roff[w];
    int e = roff[w + 1];

    float4 acc = make_float4(0.f, 0.f, 0.f, 0.f);

    int i = s + half;
    int fn = (i < e) ? __ldg(&nbr[i]) : 0;
    while (i < e) {
        int f = fn;
        int inext = i + 2;
        if (inext < e) fn = __ldg(&nbr[inext]);       // prefetch next index
        float sc = __ldg(&inv_src[f]);
        float4 v = __ldg(&xsrc[f * 16 + l]);
        acc.x = fmaf(sc, v.x, acc.x);
        acc.y = fmaf(sc, v.y, acc.y);
        acc.z = fmaf(sc, v.z, acc.z);
        acc.w = fmaf(sc, v.w, acc.w);
        i = inext;
    }

    __syncwarp();
    acc.x += __shfl_xor_sync(0xFFFFFFFFu, acc.x, 16);
    acc.y += __shfl_xor_sync(0xFFFFFFFFu, acc.y, 16);
    acc.z += __shfl_xor_sync(0xFFFFFFFFu, acc.z, 16);
    acc.w += __shfl_xor_sync(0xFFFFFFFFu, acc.w, 16);

    if (half == 0) {
        float4 xs = xself[w * 16 + l];
        float c = COEF * inv_self[w];
        float4 r;
        r.x = fmaf(c, acc.x, xs.x);
        r.y = fmaf(c, acc.y, xs.y);
        r.z = fmaf(c, acc.z, xs.z);
        r.w = fmaf(c, acc.w, xs.w);
        out[w * 16 + l] = r;
    }
}

// Scores: one warp per label edge, float2 per lane, warp-reduce dot.
__global__ void k_scores(const int* __restrict__ lm, const int* __restrict__ lu,
                         const float2* __restrict__ ru, const float2* __restrict__ rm,
                         float* __restrict__ out, int L) {
    int gtid = blockIdx.x * blockDim.x + threadIdx.x;
    int l    = gtid >> 5;
    int lane = threadIdx.x & 31;
    if (l >= L) return;

    int m = lm[l];
    int u = lu[l];
    float2 a = ru[u * 32 + lane];
    float2 b = rm[m * 32 + lane];
    float s = a.x * b.x + a.y * b.y;

    #pragma unroll
    for (int off = 16; off > 0; off >>= 1)
        s += __shfl_down_sync(0xFFFFFFFFu, s, off);

    if (lane == 0) out[l] = s;
}

// ---------------------------------------------------------------------------
extern "C" void kernel_launch(void* const* d_in, const int* in_sizes, int n_in,
                              void* d_out, int out_size) {
    const float* emb_user  = (const float*)d_in[0];   // [NU, 64]
    const float* emb_movie = (const float*)d_in[1];   // [NM, 64]
    const int* edge_from   = (const int*)d_in[4];     // [E] movie idx
    const int* edge_to     = (const int*)d_in[5];     // [E] user idx
    const int* label_movie = (const int*)d_in[6];     // [L]
    const int* label_user  = (const int*)d_in[7];     // [L]

    int NU = in_sizes[0] / DIM;
    int NM = in_sizes[1] / DIM;
    int E  = in_sizes[4];
    int L  = in_sizes[6];

    float* out    = (float*)d_out;
    float* scores = out;                    // [L]
    float* res_u  = out + L;                // [NU*64]
    float* res_m  = out + L + NU * DIM;     // [NM*64]

    const float4* xu4 = (const float4*)emb_user;
    const float4* xm4 = (const float4*)emb_movie;
    float4* ru4 = (float4*)res_u;
    float4* rm4 = (float4*)res_m;

    int nmax = (NU > NM) ? NU : NM;

    // device scratch pointers (symbols resolve at compile time in device code;
    // host needs addresses only for none of these — all access is in-kernel)

    k_zero_deg<<<(nmax + 255) / 256, 256>>>(NU, NM);
    k_count_deg<<<2048, 256>>>(edge_from, edge_to, E);
    k_inv<<<(nmax + 255) / 256, 256>>>(NU, NM);
    k_scan<<<2, SCAN_T>>>(NU, NM);
    k_fill<<<2048, 256>>>(edge_from, edge_to, E);

    // gather for users: neighbors are movies
    {
        int* nbr; int* roff; float* invu; float* invm;
        cudaGetSymbolAddress((void**)&nbr,  g_nbr_u);
        cudaGetSymbolAddress((void**)&roff, g_off_u);
        cudaGetSymbolAddress((void**)&invu, g_inv_u);
        cudaGetSymbolAddress((void**)&invm, g_inv_m);
        long long threads = (long long)NU * 32;
        int blocks = (int)((threads + 255) / 256);
        k_gather<<<blocks, 256>>>(nbr, roff, xm4, xu4, invu, invm, ru4, NU);
    }
    // gather for movies: neighbors are users
    {
        int* nbr; int* roff; float* invu; float* invm;
        cudaGetSymbolAddress((void**)&nbr,  g_nbr_m);
        cudaGetSymbolAddress((void**)&roff, g_off_m);
        cudaGetSymbolAddress((void**)&invu, g_inv_u);
        cudaGetSymbolAddress((void**)&invm, g_inv_m);
        long long threads = (long long)NM * 32;
        int blocks = (int)((threads + 255) / 256);
        k_gather<<<blocks, 256>>>(nbr, roff, xu4, xm4, invm, invu, rm4, NM);
    }

    {
        long long threads = (long long)L * 32;
        int blocks = (int)((threads + 255) / 256);
        k_scores<<<blocks, 256>>>(label_movie, label_user,
                                  (const float2*)res_u, (const float2*)res_m,
                                  scores, L);
    }
}

// round 3
// speedup vs baseline: 2.2876x; 1.2682x over previous
#include <cuda_runtime.h>
#include <cuda_bf16.h>
#include <cstdint>

#define MAX_NU 160000
#define MAX_NM 60000
#define MAX_E  5000000
#define DIM 64
#define COEF (13.0f / 12.0f)   // 1/2 + 1/3 + 1/4 : all layers aggregate layer-0 feats

#define SCAN_TILE 2048          // elements per scan block (256 threads x 8)
#define MAX_BU ((MAX_NU + SCAN_TILE - 1) / SCAN_TILE)   // 79
#define MAX_BM ((MAX_NM + SCAN_TILE - 1) / SCAN_TILE)   // 30

// ---- scratch (static device globals; no allocation allowed) ----------------
__device__ int   g_deg_u[MAX_NU];
__device__ int   g_deg_m[MAX_NM];
__device__ float g_inv_u[MAX_NU];
__device__ float g_inv_m[MAX_NM];
__device__ int   g_off_u[MAX_NU + 1];
__device__ int   g_off_m[MAX_NM + 1];
__device__ int   g_cur_u[MAX_NU];
__device__ int   g_cur_m[MAX_NM];
__device__ int   g_nbr_u[MAX_E];   // per user: movie neighbors
__device__ int   g_nbr_m[MAX_E];   // per movie: user neighbors
__device__ int   g_bsum_u[256];
__device__ int   g_bsum_m[128];

// ---------------------------------------------------------------------------
__global__ void k_zero_deg(int nu, int nm) {
    int i = blockIdx.x * blockDim.x + threadIdx.x;
    if (i < nu) g_deg_u[i] = 0;
    if (i < nm) g_deg_m[i] = 0;
}

__global__ void k_count_deg(const int* __restrict__ ef, const int* __restrict__ et, int E) {
    int i = blockIdx.x * blockDim.x + threadIdx.x;
    int stride = gridDim.x * blockDim.x;
    for (; i < E; i += stride) {
        atomicAdd(&g_deg_m[ef[i]], 1);
        atomicAdd(&g_deg_u[et[i]], 1);
    }
}

// ---- parallel exclusive scan, 3 phases -------------------------------------
// Phase A: per-tile local exclusive scan; tile totals -> g_bsum_*
__global__ void k_scan_part(int nu, int nm, int Bu) {
    __shared__ int sh[256];
    int b = blockIdx.x;
    const int* deg; int* off; int* bsum; int n; int lb;
    if (b < Bu) { deg = g_deg_u; off = g_off_u; bsum = g_bsum_u; n = nu; lb = b; }
    else        { deg = g_deg_m; off = g_off_m; bsum = g_bsum_m; n = nm; lb = b - Bu; }

    int t = threadIdx.x;
    int idx = lb * SCAN_TILE + t * 8;
    int v[8], s = 0;
    #pragma unroll
    for (int j = 0; j < 8; j++) {
        v[j] = (idx + j < n) ? deg[idx + j] : 0;
        s += v[j];
    }
    sh[t] = s;
    __syncthreads();
    #pragma unroll
    for (int o = 1; o < 256; o <<= 1) {
        int tmp = (t >= o) ? sh[t - o] : 0;
        __syncthreads();
        sh[t] += tmp;
        __syncthreads();
    }
    int ex = sh[t] - s;   // exclusive prefix within tile
    #pragma unroll
    for (int j = 0; j < 8; j++) {
        if (idx + j < n) off[idx + j] = ex;
        ex += v[j];
    }
    if (t == 255) bsum[lb] = sh[255];
}

// Phase B: scan the tile sums (tiny; one block, two serial lanes)
__global__ void k_scan_bsum(int Bu, int Bm, int nu, int nm) {
    if (threadIdx.x == 0) {
        int acc = 0;
        for (int i = 0; i < Bu; i++) { int v = g_bsum_u[i]; g_bsum_u[i] = acc; acc += v; }
        g_off_u[nu] = acc;
    }
    if (threadIdx.x == 1) {
        int acc = 0;
        for (int i = 0; i < Bm; i++) { int v = g_bsum_m[i]; g_bsum_m[i] = acc; acc += v; }
        g_off_m[nm] = acc;
    }
}

// Phase C: add tile prefix, copy to cursor array, and compute inv = rsqrt(deg)
__global__ void k_scan_add(int nu, int nm, int Bu) {
    int b = blockIdx.x;
    const int* deg; int* off; int* cur; float* inv; const int* bsum; int n; int lb;
    if (b < Bu) { deg = g_deg_u; off = g_off_u; cur = g_cur_u; inv = g_inv_u; bsum = g_bsum_u; n = nu; lb = b; }
    else        { deg = g_deg_m; off = g_off_m; cur = g_cur_m; inv = g_inv_m; bsum = g_bsum_m; n = nm; lb = b - Bu; }

    int add = bsum[lb];
    int idx = lb * SCAN_TILE + threadIdx.x * 8;
    #pragma unroll
    for (int j = 0; j < 8; j++) {
        int i = idx + j;
        if (i < n) {
            int o = off[i] + add;
            off[i] = o;
            cur[i] = o;
            int d = deg[i];
            inv[i] = (d > 0) ? rsqrtf((float)d) : 0.0f;
        }
    }
}

// ---- CSR fill --------------------------------------------------------------
__global__ void k_fill(const int* __restrict__ ef, const int* __restrict__ et, int E) {
    int i = blockIdx.x * blockDim.x + threadIdx.x;
    int stride = gridDim.x * blockDim.x;
    for (; i < E; i += stride) {
        int f = ef[i];   // movie
        int t = et[i];   // user
        int pu = atomicAdd(&g_cur_u[t], 1);
        g_nbr_u[pu] = f;
        int pm = atomicAdd(&g_cur_m[f], 1);
        g_nbr_m[pm] = t;
    }
}

// ---- gather: one warp per destination node ---------------------------------
// Half-warps stride neighbors by 2; 2x unrolled with dual accumulators for MLP.
// out[w] = x_self[w] + COEF * inv_self[w] * sum_f inv_src[f] * x_src[f]
__global__ void __launch_bounds__(256)
k_gather(const int* __restrict__ nbr, const int* __restrict__ roff,
         const float4* __restrict__ xsrc, const float4* __restrict__ xself,
         const float* __restrict__ inv_self, const float* __restrict__ inv_src,
         float4* __restrict__ out, int n)
{
    int gtid = blockIdx.x * blockDim.x + threadIdx.x;
    int w = gtid >> 5;
    if (w >= n) return;
    int lane = threadIdx.x & 31;
    int half = lane >> 4;
    int l    = lane & 15;

    int s = roff[w];
    int e = roff[w + 1];

    float4 acc0 = make_float4(0.f, 0.f, 0.f, 0.f);
    float4 acc1 = make_float4(0.f, 0.f, 0.f, 0.f);

    int i = s + half;
    // unrolled: two neighbors in flight per half-warp
    for (; i + 2 < e; i += 4) {
        int f0 = __ldg(&nbr[i]);
        int f1 = __ldg(&nbr[i + 2]);
        float sc0 = __ldg(&inv_src[f0]);
        float sc1 = __ldg(&inv_src[f1]);
        float4 v0 = __ldg(&xsrc[f0 * 16 + l]);
        float4 v1 = __ldg(&xsrc[f1 * 16 + l]);
        acc0.x = fmaf(sc0, v0.x, acc0.x);
        acc0.y = fmaf(sc0, v0.y, acc0.y);
        acc0.z = fmaf(sc0, v0.z, acc0.z);
        acc0.w = fmaf(sc0, v0.w, acc0.w);
        acc1.x = fmaf(sc1, v1.x, acc1.x);
        acc1.y = fmaf(sc1, v1.y, acc1.y);
        acc1.z = fmaf(sc1, v1.z, acc1.z);
        acc1.w = fmaf(sc1, v1.w, acc1.w);
    }
    for (; i < e; i += 2) {
        int f = __ldg(&nbr[i]);
        float sc = __ldg(&inv_src[f]);
        float4 v = __ldg(&xsrc[f * 16 + l]);
        acc0.x = fmaf(sc, v.x, acc0.x);
        acc0.y = fmaf(sc, v.y, acc0.y);
        acc0.z = fmaf(sc, v.z, acc0.z);
        acc0.w = fmaf(sc, v.w, acc0.w);
    }
    acc0.x += acc1.x; acc0.y += acc1.y; acc0.z += acc1.z; acc0.w += acc1.w;

    __syncwarp();
    acc0.x += __shfl_xor_sync(0xFFFFFFFFu, acc0.x, 16);
    acc0.y += __shfl_xor_sync(0xFFFFFFFFu, acc0.y, 16);
    acc0.z += __shfl_xor_sync(0xFFFFFFFFu, acc0.z, 16);
    acc0.w += __shfl_xor_sync(0xFFFFFFFFu, acc0.w, 16);

    if (half == 0) {
        float4 xs = xself[w * 16 + l];
        float c = COEF * inv_self[w];
        float4 r;
        r.x = fmaf(c, acc0.x, xs.x);
        r.y = fmaf(c, acc0.y, xs.y);
        r.z = fmaf(c, acc0.z, xs.z);
        r.w = fmaf(c, acc0.w, xs.w);
        out[w * 16 + l] = r;
    }
}

// ---- scores ----------------------------------------------------------------
__global__ void k_scores(const int* __restrict__ lm, const int* __restrict__ lu,
                         const float2* __restrict__ ru, const float2* __restrict__ rm,
                         float* __restrict__ out, int L) {
    int gtid = blockIdx.x * blockDim.x + threadIdx.x;
    int l    = gtid >> 5;
    int lane = threadIdx.x & 31;
    if (l >= L) return;

    int m = lm[l];
    int u = lu[l];
    float2 a = ru[u * 32 + lane];
    float2 b = rm[m * 32 + lane];
    float s = a.x * b.x + a.y * b.y;

    #pragma unroll
    for (int off = 16; off > 0; off >>= 1)
        s += __shfl_down_sync(0xFFFFFFFFu, s, off);

    if (lane == 0) out[l] = s;
}

// ---------------------------------------------------------------------------
extern "C" void kernel_launch(void* const* d_in, const int* in_sizes, int n_in,
                              void* d_out, int out_size) {
    const float* emb_user  = (const float*)d_in[0];   // [NU, 64]
    const float* emb_movie = (const float*)d_in[1];   // [NM, 64]
    const int* edge_from   = (const int*)d_in[4];     // [E] movie idx
    const int* edge_to     = (const int*)d_in[5];     // [E] user idx
    const int* label_movie = (const int*)d_in[6];     // [L]
    const int* label_user  = (const int*)d_in[7];     // [L]

    int NU = in_sizes[0] / DIM;
    int NM = in_sizes[1] / DIM;
    int E  = in_sizes[4];
    int L  = in_sizes[6];

    float* out    = (float*)d_out;
    float* scores = out;                    // [L]
    float* res_u  = out + L;                // [NU*64]
    float* res_m  = out + L + NU * DIM;     // [NM*64]

    const float4* xu4 = (const float4*)emb_user;
    const float4* xm4 = (const float4*)emb_movie;
    float4* ru4 = (float4*)res_u;
    float4* rm4 = (float4*)res_m;

    int nmax = (NU > NM) ? NU : NM;
    int Bu = (NU + SCAN_TILE - 1) / SCAN_TILE;
    int Bm = (NM + SCAN_TILE - 1) / SCAN_TILE;

    k_zero_deg<<<(nmax + 255) / 256, 256>>>(NU, NM);
    k_count_deg<<<2048, 256>>>(edge_from, edge_to, E);
    k_scan_part<<<Bu + Bm, 256>>>(NU, NM, Bu);
    k_scan_bsum<<<1, 32>>>(Bu, Bm, NU, NM);
    k_scan_add<<<Bu + Bm, 256>>>(NU, NM, Bu);
    k_fill<<<2048, 256>>>(edge_from, edge_to, E);

    // gather for users: neighbors are movies
    {
        int* nbr; int* roff; float* invu; float* invm;
        cudaGetSymbolAddress((void**)&nbr,  g_nbr_u);
        cudaGetSymbolAddress((void**)&roff, g_off_u);
        cudaGetSymbolAddress((void**)&invu, g_inv_u);
        cudaGetSymbolAddress((void**)&invm, g_inv_m);
        long long threads = (long long)NU * 32;
        int blocks = (int)((threads + 255) / 256);
        k_gather<<<blocks, 256>>>(nbr, roff, xm4, xu4, invu, invm, ru4, NU);
    }
    // gather for movies: neighbors are users
    {
        int* nbr; int* roff; float* invu; float* invm;
        cudaGetSymbolAddress((void**)&nbr,  g_nbr_m);
        cudaGetSymbolAddress((void**)&roff, g_off_m);
        cudaGetSymbolAddress((void**)&invu, g_inv_u);
        cudaGetSymbolAddress((void**)&invm, g_inv_m);
        long long threads = (long long)NM * 32;
        int blocks = (int)((threads + 255) / 256);
        k_gather<<<blocks, 256>>>(nbr, roff, xu4, xm4, invm, invu, rm4, NM);
    }

    {
        long long threads = (long long)L * 32;
        int blocks = (int)((threads + 255) / 256);
        k_scores<<<blocks, 256>>>(label_movie, label_user,
                                  (const float2*)res_u, (const float2*)res_m,
                                  scores, L);
    }
}

// round 4
// speedup vs baseline: 2.4035x; 1.0507x over previous
#include <cuda_runtime.h>
#include <cuda_bf16.h>
#include <cstdint>

#define MAX_NU 160000
#define MAX_NM 60000
#define MAX_E  5000000
#define DIM 64
#define COEF (13.0f / 12.0f)   // 1/2 + 1/3 + 1/4 : all layers aggregate layer-0 feats

#define SCAN_TILE 2048          // elements per scan block (256 threads x 8)

// ---- scratch (static device globals; no allocation allowed) ----------------
__device__ int   g_deg_u[MAX_NU];
__device__ int   g_deg_m[MAX_NM];
__device__ float g_inv_u[MAX_NU];
__device__ float g_inv_m[MAX_NM];
__device__ int   g_off_u[MAX_NU + 1];
__device__ int   g_off_m[MAX_NM + 1];
__device__ int   g_cur_u[MAX_NU];
__device__ int   g_cur_m[MAX_NM];
__device__ int   g_nbr_u[MAX_E];    // per user: movie neighbors
__device__ int   g_nbr_m[MAX_E];    // per movie: user neighbors
__device__ int   g_bsum_u[256];
__device__ int   g_bsum_m[128];
// bf16 staged source rows, PRE-SCALED by inv_src. Row = 64 bf16 = 128 bytes.
__device__ uint2 g_xm_bf[MAX_NM * 16];   // 60000*16*8B  = 7.68 MB
__device__ uint2 g_xu_bf[MAX_NU * 16];   // 160000*16*8B = 20.5 MB

// ---------------------------------------------------------------------------
__global__ void k_zero_deg(int nu, int nm) {
    int i = blockIdx.x * blockDim.x + threadIdx.x;
    if (i < nu) g_deg_u[i] = 0;
    if (i < nm) g_deg_m[i] = 0;
}

__global__ void k_count_deg(const int* __restrict__ ef, const int* __restrict__ et, int E) {
    int i = blockIdx.x * blockDim.x + threadIdx.x;
    int stride = gridDim.x * blockDim.x;
    for (; i < E; i += stride) {
        atomicAdd(&g_deg_m[ef[i]], 1);
        atomicAdd(&g_deg_u[et[i]], 1);
    }
}

// ---- parallel exclusive scan, 3 phases -------------------------------------
__global__ void k_scan_part(int nu, int nm, int Bu) {
    __shared__ int sh[256];
    int b = blockIdx.x;
    const int* deg; int* off; int* bsum; int n; int lb;
    if (b < Bu) { deg = g_deg_u; off = g_off_u; bsum = g_bsum_u; n = nu; lb = b; }
    else        { deg = g_deg_m; off = g_off_m; bsum = g_bsum_m; n = nm; lb = b - Bu; }

    int t = threadIdx.x;
    int idx = lb * SCAN_TILE + t * 8;
    int v[8], s = 0;
    #pragma unroll
    for (int j = 0; j < 8; j++) {
        v[j] = (idx + j < n) ? deg[idx + j] : 0;
        s += v[j];
    }
    sh[t] = s;
    __syncthreads();
    #pragma unroll
    for (int o = 1; o < 256; o <<= 1) {
        int tmp = (t >= o) ? sh[t - o] : 0;
        __syncthreads();
        sh[t] += tmp;
        __syncthreads();
    }
    int ex = sh[t] - s;
    #pragma unroll
    for (int j = 0; j < 8; j++) {
        if (idx + j < n) off[idx + j] = ex;
        ex += v[j];
    }
    if (t == 255) bsum[lb] = sh[255];
}

__global__ void k_scan_bsum(int Bu, int Bm, int nu, int nm) {
    if (threadIdx.x == 0) {
        int acc = 0;
        for (int i = 0; i < Bu; i++) { int v = g_bsum_u[i]; g_bsum_u[i] = acc; acc += v; }
        g_off_u[nu] = acc;
    }
    if (threadIdx.x == 1) {
        int acc = 0;
        for (int i = 0; i < Bm; i++) { int v = g_bsum_m[i]; g_bsum_m[i] = acc; acc += v; }
        g_off_m[nm] = acc;
    }
}

__global__ void k_scan_add(int nu, int nm, int Bu) {
    int b = blockIdx.x;
    const int* deg; int* off; int* cur; float* inv; const int* bsum; int n; int lb;
    if (b < Bu) { deg = g_deg_u; off = g_off_u; cur = g_cur_u; inv = g_inv_u; bsum = g_bsum_u; n = nu; lb = b; }
    else        { deg = g_deg_m; off = g_off_m; cur = g_cur_m; inv = g_inv_m; bsum = g_bsum_m; n = nm; lb = b - Bu; }

    int add = bsum[lb];
    int idx = lb * SCAN_TILE + threadIdx.x * 8;
    #pragma unroll
    for (int j = 0; j < 8; j++) {
        int i = idx + j;
        if (i < n) {
            int o = off[i] + add;
            off[i] = o;
            cur[i] = o;
            int d = deg[i];
            inv[i] = (d > 0) ? rsqrtf((float)d) : 0.0f;
        }
    }
}

// ---- convert: stage pre-scaled bf16 rows -----------------------------------
// thread handles one float4 chunk (4 dims) of one node row.
__global__ void k_convert(const float4* __restrict__ xu, const float4* __restrict__ xm,
                          int nu, int nm) {
    int i = blockIdx.x * blockDim.x + threadIdx.x;
    int total_u = nu * 16;
    int total   = total_u + nm * 16;
    if (i >= total) return;
    const float4* src; const float* inv; uint2* dst; int node, chunk;
    if (i < total_u) { src = xu; inv = g_inv_u; dst = g_xu_bf; node = i >> 4; chunk = i & 15; }
    else { int j = i - total_u; src = xm; inv = g_inv_m; dst = g_xm_bf; node = j >> 4; chunk = j & 15; }

    float sc = inv[node];
    float4 v = src[node * 16 + chunk];
    __nv_bfloat162 b0 = __floats2bfloat162_rn(sc * v.x, sc * v.y);
    __nv_bfloat162 b1 = __floats2bfloat162_rn(sc * v.z, sc * v.w);
    uint2 p;
    p.x = *(unsigned int*)&b0;
    p.y = *(unsigned int*)&b1;
    dst[node * 16 + chunk] = p;
}

// ---- CSR fill --------------------------------------------------------------
__global__ void k_fill(const int* __restrict__ ef, const int* __restrict__ et, int E) {
    int i = blockIdx.x * blockDim.x + threadIdx.x;
    int stride = gridDim.x * blockDim.x;
    for (; i < E; i += stride) {
        int f = ef[i];   // movie
        int t = et[i];   // user
        int pu = atomicAdd(&g_cur_u[t], 1);
        g_nbr_u[pu] = f;
        int pm = atomicAdd(&g_cur_m[f], 1);
        g_nbr_m[pm] = t;
    }
}

// ---- merged gather: one warp per destination node (users then movies) ------
// Source rows are pre-scaled bf16 (128B). Half-warps stride neighbors by 2,
// 2x unrolled => up to 4 rows in flight per warp. fp32 accumulation.
// out[w] = x_self[w] + COEF * inv_self[w] * sum_f staged_src[f]
__global__ void __launch_bounds__(256)
k_gather_all(const float4* __restrict__ xu, const float4* __restrict__ xm,
             float4* __restrict__ ru, float4* __restrict__ rm,
             int nu, int nm)
{
    int gtid = blockIdx.x * blockDim.x + threadIdx.x;
    int w = gtid >> 5;
    if (w >= nu + nm) return;
    int lane = threadIdx.x & 31;
    int half = lane >> 4;
    int l    = lane & 15;

    const int* nbr; const int* roff; const uint2* src;
    const float4* xself; const float* inv_self; float4* out; int node;
    if (w < nu) {
        node = w; nbr = g_nbr_u; roff = g_off_u; src = g_xm_bf;
        xself = xu; inv_self = g_inv_u; out = ru;
    } else {
        node = w - nu; nbr = g_nbr_m; roff = g_off_m; src = g_xu_bf;
        xself = xm; inv_self = g_inv_m; out = rm;
    }

    int s = roff[node];
    int e = roff[node + 1];

    float4 acc0 = make_float4(0.f, 0.f, 0.f, 0.f);
    float4 acc1 = make_float4(0.f, 0.f, 0.f, 0.f);

    int i = s + half;
    for (; i + 2 < e; i += 4) {
        int f0 = __ldg(&nbr[i]);
        int f1 = __ldg(&nbr[i + 2]);
        uint2 p0 = __ldg(&src[f0 * 16 + l]);
        uint2 p1 = __ldg(&src[f1 * 16 + l]);
        float2 a0 = __bfloat1622float2(*(__nv_bfloat162*)&p0.x);
        float2 a1 = __bfloat1622float2(*(__nv_bfloat162*)&p0.y);
        float2 b0 = __bfloat1622float2(*(__nv_bfloat162*)&p1.x);
        float2 b1 = __bfloat1622float2(*(__nv_bfloat162*)&p1.y);
        acc0.x += a0.x; acc0.y += a0.y; acc0.z += a1.x; acc0.w += a1.y;
        acc1.x += b0.x; acc1.y += b0.y; acc1.z += b1.x; acc1.w += b1.y;
    }
    for (; i < e; i += 2) {
        int f = __ldg(&nbr[i]);
        uint2 p = __ldg(&src[f * 16 + l]);
        float2 a0 = __bfloat1622float2(*(__nv_bfloat162*)&p.x);
        float2 a1 = __bfloat1622float2(*(__nv_bfloat162*)&p.y);
        acc0.x += a0.x; acc0.y += a0.y; acc0.z += a1.x; acc0.w += a1.y;
    }
    acc0.x += acc1.x; acc0.y += acc1.y; acc0.z += acc1.z; acc0.w += acc1.w;

    __syncwarp();
    acc0.x += __shfl_xor_sync(0xFFFFFFFFu, acc0.x, 16);
    acc0.y += __shfl_xor_sync(0xFFFFFFFFu, acc0.y, 16);
    acc0.z += __shfl_xor_sync(0xFFFFFFFFu, acc0.z, 16);
    acc0.w += __shfl_xor_sync(0xFFFFFFFFu, acc0.w, 16);

    if (half == 0) {
        float4 xs = xself[node * 16 + l];
        float c = COEF * inv_self[node];
        float4 r;
        r.x = fmaf(c, acc0.x, xs.x);
        r.y = fmaf(c, acc0.y, xs.y);
        r.z = fmaf(c, acc0.z, xs.z);
        r.w = fmaf(c, acc0.w, xs.w);
        out[node * 16 + l] = r;
    }
}

// ---- scores ----------------------------------------------------------------
__global__ void k_scores(const int* __restrict__ lm, const int* __restrict__ lu,
                         const float2* __restrict__ ru, const float2* __restrict__ rm,
                         float* __restrict__ out, int L) {
    int gtid = blockIdx.x * blockDim.x + threadIdx.x;
    int l    = gtid >> 5;
    int lane = threadIdx.x & 31;
    if (l >= L) return;

    int m = lm[l];
    int u = lu[l];
    float2 a = ru[u * 32 + lane];
    float2 b = rm[m * 32 + lane];
    float s = a.x * b.x + a.y * b.y;

    #pragma unroll
    for (int off = 16; off > 0; off >>= 1)
        s += __shfl_down_sync(0xFFFFFFFFu, s, off);

    if (lane == 0) out[l] = s;
}

// ---------------------------------------------------------------------------
extern "C" void kernel_launch(void* const* d_in, const int* in_sizes, int n_in,
                              void* d_out, int out_size) {
    const float* emb_user  = (const float*)d_in[0];   // [NU, 64]
    const float* emb_movie = (const float*)d_in[1];   // [NM, 64]
    const int* edge_from   = (const int*)d_in[4];     // [E] movie idx
    const int* edge_to     = (const int*)d_in[5];     // [E] user idx
    const int* label_movie = (const int*)d_in[6];     // [L]
    const int* label_user  = (const int*)d_in[7];     // [L]

    int NU = in_sizes[0] / DIM;
    int NM = in_sizes[1] / DIM;
    int E  = in_sizes[4];
    int L  = in_sizes[6];

    float* out    = (float*)d_out;
    float* scores = out;                    // [L]
    float* res_u  = out + L;                // [NU*64]
    float* res_m  = out + L + NU * DIM;     // [NM*64]

    const float4* xu4 = (const float4*)emb_user;
    const float4* xm4 = (const float4*)emb_movie;
    float4* ru4 = (float4*)res_u;
    float4* rm4 = (float4*)res_m;

    int nmax = (NU > NM) ? NU : NM;
    int Bu = (NU + SCAN_TILE - 1) / SCAN_TILE;
    int Bm = (NM + SCAN_TILE - 1) / SCAN_TILE;

    k_zero_deg<<<(nmax + 255) / 256, 256>>>(NU, NM);
    k_count_deg<<<2048, 256>>>(edge_from, edge_to, E);
    k_scan_part<<<Bu + Bm, 256>>>(NU, NM, Bu);
    k_scan_bsum<<<1, 32>>>(Bu, Bm, NU, NM);
    k_scan_add<<<Bu + Bm, 256>>>(NU, NM, Bu);

    // stage pre-scaled bf16 rows (needs inv; independent of fill)
    {
        int total = (NU + NM) * 16;
        k_convert<<<(total + 255) / 256, 256>>>(xu4, xm4, NU, NM);
    }

    k_fill<<<2048, 256>>>(edge_from, edge_to, E);

    // merged gather (users + movies)
    {
        long long threads = (long long)(NU + NM) * 32;
        int blocks = (int)((threads + 255) / 256);
        k_gather_all<<<blocks, 256>>>(xu4, xm4, ru4, rm4, NU, NM);
    }

    {
        long long threads = (long long)L * 32;
        int blocks = (int)((threads + 255) / 256);
        k_scores<<<blocks, 256>>>(label_movie, label_user,
                                  (const float2*)res_u, (const float2*)res_m,
                                  scores, L);
    }
}